// round 8
// baseline (speedup 1.0000x reference)
#include <cuda_runtime.h>
#include <cuda_bf16.h>
#include <math.h>
#include <cstdint>

#define D   64
#define NC  10
#define NS  4096

// final cluster centers handed from kernel A to kernel B
__device__ __align__(16) float g_cc[NC * D];

__device__ __forceinline__ void cp_async16(float* dst_smem, const float4* src) {
    unsigned int dst = (unsigned int)__cvta_generic_to_shared(dst_smem);
    asm volatile("cp.async.cg.shared.global [%0], [%1], 16;" :: "r"(dst), "l"(src));
}

__device__ __forceinline__ float fast_sigmoid(float x) {
    return 1.f / (1.f + __expf(-x));          // saturates cleanly at +/-inf
}
__device__ __forceinline__ float fast_tanh(float x) {
    float e2 = __expf(2.f * x);
    return 1.f - 2.f / (e2 + 1.f);            // no NaN at overflow
}

// ---------------------------------------------------------------------------
// Kernel A: all weights streamed to smem via cp.async ONCE; k/v computed
// directly from gmem under the stream; 3 iterations entirely from smem.
// Dynamic smem layout (floats):
//   wq[64x68]@0  wih[192x68]@4352  whh[192x68]@17408  w1[128x68]@30464
//   w2[64x132]@39168  scc@47616 sk@48256 sv@48896 sq@49536 sxu@50176 (640 ea)
//   sgi@50816(1920) sgh@52736(1920) sattn@54656(128) sred@54784(32)
// total 54816 floats = 219264 bytes
// ---------------------------------------------------------------------------
#define SMEM_A_FLOATS 54816
#define SMEM_A_BYTES  (SMEM_A_FLOATS * 4)

template<int R, int C>
__device__ __forceinline__ void stage_async(const float* __restrict__ W, float* s, int t) {
    const float4* g4 = (const float4*)W;
    constexpr int NF4 = R * C / 4;
    #pragma unroll
    for (int f = t; f < NF4; f += 640) {
        int r = (4 * f) / C;
        int c = (4 * f) % C;
        cp_async16(s + r * (C + 4) + c, g4 + f);
    }
}

// out[n][o] = act( X[n][:] . sW[o][:] + B[o] )  for n in [n0, n0+5)
// thread t < ODIM*2: o = t % ODIM, n0 = (t/ODIM)*5.  Dual accumulator chains
// per cluster for ILP; X reads are warp-uniform broadcasts.
template<int ODIM, int INNER, int ACT>
__device__ __forceinline__ void mmr(const float* __restrict__ X,
                                    const float* __restrict__ sW,
                                    const float* __restrict__ B,
                                    float* __restrict__ out, int t) {
    constexpr int STR = INNER + 4;
    if (t < ODIM * 2) {
        int o  = t % ODIM;
        int n0 = (t / ODIM) * 5;
        const float* w  = sW + o * STR;
        const float* xb = X + n0 * INNER;
        float a0x=0.f,a0y=0.f,a1x=0.f,a1y=0.f,a2x=0.f,a2y=0.f,a3x=0.f,a3y=0.f,a4x=0.f,a4y=0.f;
        #pragma unroll
        for (int j = 0; j < INNER; j += 4) {
            float4 wv = *(const float4*)(w + j);
            float4 x0 = *(const float4*)(xb + j);
            float4 x1 = *(const float4*)(xb + INNER + j);
            float4 x2 = *(const float4*)(xb + 2 * INNER + j);
            float4 x3 = *(const float4*)(xb + 3 * INNER + j);
            float4 x4 = *(const float4*)(xb + 4 * INNER + j);
            a0x = fmaf(wv.x, x0.x, fmaf(wv.z, x0.z, a0x));
            a0y = fmaf(wv.y, x0.y, fmaf(wv.w, x0.w, a0y));
            a1x = fmaf(wv.x, x1.x, fmaf(wv.z, x1.z, a1x));
            a1y = fmaf(wv.y, x1.y, fmaf(wv.w, x1.w, a1y));
            a2x = fmaf(wv.x, x2.x, fmaf(wv.z, x2.z, a2x));
            a2y = fmaf(wv.y, x2.y, fmaf(wv.w, x2.w, a2y));
            a3x = fmaf(wv.x, x3.x, fmaf(wv.z, x3.z, a3x));
            a3y = fmaf(wv.y, x3.y, fmaf(wv.w, x3.w, a3y));
            a4x = fmaf(wv.x, x4.x, fmaf(wv.z, x4.z, a4x));
            a4y = fmaf(wv.y, x4.y, fmaf(wv.w, x4.w, a4y));
        }
        float bo = B[o];
        float r0 = a0x + a0y + bo, r1 = a1x + a1y + bo, r2 = a2x + a2y + bo;
        float r3 = a3x + a3y + bo, r4 = a4x + a4y + bo;
        if (ACT) {
            r0 = fmaxf(r0, 0.f); r1 = fmaxf(r1, 0.f); r2 = fmaxf(r2, 0.f);
            r3 = fmaxf(r3, 0.f); r4 = fmaxf(r4, 0.f);
        }
        out[(n0 + 0) * ODIM + o] = r0;
        out[(n0 + 1) * ODIM + o] = r1;
        out[(n0 + 2) * ODIM + o] = r2;
        out[(n0 + 3) * ODIM + o] = r3;
        out[(n0 + 4) * ODIM + o] = r4;
    }
}

// layernorm over last dim, warp-shuffle reduction (10 warps of 320 threads)
__device__ __forceinline__ void lnw(const float* __restrict__ X,
                                    const float* __restrict__ gma,
                                    const float* __restrict__ bta,
                                    float* __restrict__ out,
                                    float* sred, int t) {
    if (t < 320) {
        int w = t >> 5, l = t & 31;
        float v0 = X[w * 64 + l], v1 = X[w * 64 + 32 + l];
        float s = v0 + v1, s2 = v0 * v0 + v1 * v1;
        #pragma unroll
        for (int off = 16; off; off >>= 1) {
            s  += __shfl_xor_sync(0xffffffffu, s, off);
            s2 += __shfl_xor_sync(0xffffffffu, s2, off);
        }
        if (l == 0) {
            float m = s * (1.f / 64.f);
            sred[w]      = m;
            sred[16 + w] = rsqrtf(s2 * (1.f / 64.f) - m * m + 1e-5f);
        }
    }
    __syncthreads();
    int n = t >> 6, ii = t & 63;
    out[t] = (X[t] - sred[n]) * sred[16 + n] * gma[ii] + bta[ii];
    __syncthreads();
}

__global__ void __launch_bounds__(640)
iter_kernel(const float* __restrict__ cc0,
            const float* __restrict__ Wk, const float* __restrict__ bk,
            const float* __restrict__ Wq, const float* __restrict__ bq,
            const float* __restrict__ Wv, const float* __restrict__ bv,
            const float* __restrict__ cc_g, const float* __restrict__ cc_b,
            const float* __restrict__ W_ih, const float* __restrict__ W_hh,
            const float* __restrict__ b_ih, const float* __restrict__ b_hh,
            const float* __restrict__ ln_g, const float* __restrict__ ln_b,
            const float* __restrict__ W1, const float* __restrict__ b1,
            const float* __restrict__ W2, const float* __restrict__ b2) {
    extern __shared__ float sm[];
    float* swq  = sm;
    float* swih = sm + 4352;
    float* swhh = sm + 17408;
    float* sw1  = sm + 30464;
    float* sw2  = sm + 39168;
    float* scc  = sm + 47616;
    float* sk   = sm + 48256;
    float* sv   = sm + 48896;
    float* sq   = sm + 49536;
    float* sxu  = sm + 50176;
    float* sgi  = sm + 50816;
    float* sgh  = sm + 52736;
    float* sattn= sm + 54656;
    float* sred = sm + 54784;

    const int t  = threadIdx.x;
    const int n  = t >> 6;
    const int ii = t & 63;

    // 1. stream all persistent weights into smem (fire-and-forget)
    stage_async<64,  64 >(Wq,   swq,  t);
    stage_async<192, 64 >(W_ih, swih, t);
    stage_async<192, 64 >(W_hh, swhh, t);
    stage_async<128, 64 >(W1,   sw1,  t);
    stage_async<64,  128>(W2,   sw2,  t);
    asm volatile("cp.async.commit_group;");

    scc[t] = cc0[t];

    // 2. k, v directly from gmem (overlaps the cp.async stream)
    {
        const float4* ccr = (const float4*)(cc0 + n * 64);
        const float4* wkr = (const float4*)(Wk  + ii * 64);
        const float4* wvr = (const float4*)(Wv  + ii * 64);
        float kx = 0.f, ky = 0.f, vx = 0.f, vy = 0.f;
        #pragma unroll
        for (int j = 0; j < 16; j++) {
            float4 c4 = ccr[j];
            float4 k4 = wkr[j];
            float4 v4 = wvr[j];
            kx = fmaf(c4.x, k4.x, fmaf(c4.z, k4.z, kx));
            ky = fmaf(c4.y, k4.y, fmaf(c4.w, k4.w, ky));
            vx = fmaf(c4.x, v4.x, fmaf(c4.z, v4.z, vx));
            vy = fmaf(c4.y, v4.y, fmaf(c4.w, v4.w, vy));
        }
        sk[t] = kx + ky + bk[ii];
        sv[t] = vx + vy + bv[ii];
    }

    asm volatile("cp.async.wait_group 0;" ::: "memory");
    __syncthreads();

    for (int it = 0; it < 3; it++) {
        // ---- q = LN(cc; cc_g, cc_b) @ Wq^T + bq
        lnw(scc, cc_g, cc_b, sxu, sred, t);
        mmr<64, 64, 0>(sxu, swq, bq, sq, t);
        __syncthreads();

        // ---- attn logits: attn[an][am] = k[an].q[am] / 8
        if (t < 100) {
            int an = t / 10, am = t % 10;
            const float* kr = sk + an * D;
            const float* qr = sq + am * D;
            float ax = 0.f, ay = 0.f, az = 0.f, aw = 0.f;
            #pragma unroll
            for (int j = 0; j < D; j += 4) {
                float4 kv = *(const float4*)(kr + j);
                float4 qv = *(const float4*)(qr + j);
                ax = fmaf(kv.x, qv.x, ax);
                ay = fmaf(kv.y, qv.y, ay);
                az = fmaf(kv.z, qv.z, az);
                aw = fmaf(kv.w, qv.w, aw);
            }
            sattn[an * 10 + am] = ((ax + ay) + (az + aw)) * 0.125f;
        }
        __syncthreads();
        // softmax over axis 0 (rows an), column m = t
        if (t < 10) {
            float mx = -1e30f;
            #pragma unroll
            for (int a = 0; a < 10; a++) mx = fmaxf(mx, sattn[a * 10 + t]);
            float ss = 0.f;
            #pragma unroll
            for (int a = 0; a < 10; a++) {
                float e = __expf(sattn[a * 10 + t] - mx);
                sattn[a * 10 + t] = e;
                ss += e;
            }
            float inv = 1.f / ss;
            #pragma unroll
            for (int a = 0; a < 10; a++)
                sattn[a * 10 + t] = sattn[a * 10 + t] * inv + 1e-8f;
        }
        __syncthreads();
        // renormalize rows (axis -1), row an = t
        if (t < 10) {
            float ss = 0.f;
            #pragma unroll
            for (int m = 0; m < 10; m++) ss += sattn[t * 10 + m];
            float inv = 1.f / ss;
            #pragma unroll
            for (int m = 0; m < 10; m++) sattn[t * 10 + m] *= inv;
        }
        __syncthreads();
        // updates = attn @ v  -> sxu
        {
            float u = 0.f;
            #pragma unroll
            for (int m = 0; m < 10; m++)
                u = fmaf(sattn[n * 10 + m], sv[m * D + ii], u);
            sxu[t] = u;
        }
        __syncthreads();

        // ---- GRU gates (gi from updates, gh from cc_prev; independent)
        mmr<192, 64, 0>(sxu, swih, b_ih, sgi, t);
        mmr<192, 64, 0>(scc, swhh, b_hh, sgh, t);
        __syncthreads();
        {
            float ir  = sgi[n * 192 + ii];
            float iz  = sgi[n * 192 + 64 + ii];
            float in_ = sgi[n * 192 + 128 + ii];
            float hr  = sgh[n * 192 + ii];
            float hz  = sgh[n * 192 + 64 + ii];
            float hn  = sgh[n * 192 + 128 + ii];
            float r  = fast_sigmoid(ir + hr);
            float z  = fast_sigmoid(iz + hz);
            float nn = fast_tanh(in_ + r * hn);
            scc[t] = (1.f - z) * nn + z * scc[t];
        }
        __syncthreads();

        // ---- residual MLP: cc += relu(LN(cc) @ W1^T + b1) @ W2^T + b2
        lnw(scc, ln_g, ln_b, sxu, sred, t);
        mmr<128, 64, 1>(sxu, sw1, b1, sgi, t);   // h1 [10,128]
        __syncthreads();
        mmr<64, 128, 0>(sgi, sw2, b2, sgh, t);   // delta [10,64]
        __syncthreads();
        scc[t] += sgh[t];
        __syncthreads();
    }

    g_cc[t] = scc[t];
}

// ---------------------------------------------------------------------------
// Kernel B: PERSISTENT per-slot 2-layer MLP + max. 456 blocks (3/SM),
// double-buffered cp.async weight streaming; scc loaded once per block.
// Dyn smem floats: buf[2] x (Wa 4352 + Wb 4352) = 17408, scc@17408(640),
// sh@18048(640), smax@18688(128) -> 18816 floats = 75264 B.
// ---------------------------------------------------------------------------
#define MLP_NBLK  456
#define SMEM_B_FLOATS 18816
#define SMEM_B_BYTES  (SMEM_B_FLOATS * 4)

__global__ void __launch_bounds__(128)
mlp_kernel(const float* __restrict__ Wa, const float* __restrict__ ba,
           const float* __restrict__ Wb, const float* __restrict__ bb,
           float* __restrict__ out) {
    extern __shared__ float ms[];
    float* scc  = ms + 17408;
    float* sh   = ms + 18048;
    float* smax = ms + 18688;

    const int t = threadIdx.x;
    const int i = t & 63;
    const int g = t >> 6;

    // slot range for this block (contiguous chunks)
    const int b  = blockIdx.x;
    const int q  = NS / MLP_NBLK;                 // 8
    const int r  = NS % MLP_NBLK;                 // 448
    const int s0 = b * q + (b < r ? b : r);
    const int s1 = s0 + q + (b < r ? 1 : 0);

    // scc once per block
    #pragma unroll
    for (int p = t; p < 160; p += 128)
        ((float4*)scc)[p] = ((const float4*)g_cc)[p];

    // prefetch first slot into buffer 0 (one commit group per slot: Wa+Wb)
    {
        const float4* ga = (const float4*)(Wa + (size_t)s0 * 4096);
        const float4* gb = (const float4*)(Wb + (size_t)s0 * 4096);
        float* dWa = ms;            // buf 0
        float* dWb = ms + 4352;
        #pragma unroll
        for (int p = 0; p < 8; p++) {
            int f = t + p * 128;
            int rr = f >> 4;
            int cc = (f & 15) << 2;
            cp_async16(dWa + rr * 68 + cc, ga + f);
            cp_async16(dWb + rr * 68 + cc, gb + f);
        }
        asm volatile("cp.async.commit_group;");
    }

    int buf = 0;
    for (int s = s0; s < s1; s++, buf ^= 1) {
        // prefetch next slot into the other buffer
        if (s + 1 < s1) {
            const float4* ga = (const float4*)(Wa + (size_t)(s + 1) * 4096);
            const float4* gb = (const float4*)(Wb + (size_t)(s + 1) * 4096);
            float* dWa = ms + (buf ^ 1) * 8704;
            float* dWb = dWa + 4352;
            #pragma unroll
            for (int p = 0; p < 8; p++) {
                int f = t + p * 128;
                int rr = f >> 4;
                int cc = (f & 15) << 2;
                cp_async16(dWa + rr * 68 + cc, ga + f);
                cp_async16(dWb + rr * 68 + cc, gb + f);
            }
            asm volatile("cp.async.commit_group;");
            asm volatile("cp.async.wait_group 1;" ::: "memory");
        } else {
            asm volatile("cp.async.wait_group 0;" ::: "memory");
        }
        __syncthreads();   // slot s weights ready; also covers scc / smax reuse

        const float* sWa = ms + buf * 8704;
        const float* sWb = sWa + 4352;
        float bav = ba[(s << 6) + i];
        float bbv = bb[(s << 6) + i];

        // ---- stage 1: h[nn][i] = relu(Wa[i,:] . cc[nn,:] + ba[i]) for 5 nn
        {
            const float* wr = sWa + i * 68;
            const float* cb = scc + g * 5 * D;
            float a0x=0.f,a0y=0.f,a1x=0.f,a1y=0.f,a2x=0.f,a2y=0.f,a3x=0.f,a3y=0.f,a4x=0.f,a4y=0.f;
            #pragma unroll
            for (int j = 0; j < D; j += 4) {
                float4 w  = *(const float4*)(wr + j);
                float4 c0 = *(const float4*)(cb + j);
                float4 c1 = *(const float4*)(cb + D + j);
                float4 c2 = *(const float4*)(cb + 2 * D + j);
                float4 c3 = *(const float4*)(cb + 3 * D + j);
                float4 c4 = *(const float4*)(cb + 4 * D + j);
                a0x = fmaf(w.x, c0.x, fmaf(w.z, c0.z, a0x));
                a0y = fmaf(w.y, c0.y, fmaf(w.w, c0.w, a0y));
                a1x = fmaf(w.x, c1.x, fmaf(w.z, c1.z, a1x));
                a1y = fmaf(w.y, c1.y, fmaf(w.w, c1.w, a1y));
                a2x = fmaf(w.x, c2.x, fmaf(w.z, c2.z, a2x));
                a2y = fmaf(w.y, c2.y, fmaf(w.w, c2.w, a2y));
                a3x = fmaf(w.x, c3.x, fmaf(w.z, c3.z, a3x));
                a3y = fmaf(w.y, c3.y, fmaf(w.w, c3.w, a3y));
                a4x = fmaf(w.x, c4.x, fmaf(w.z, c4.z, a4x));
                a4y = fmaf(w.y, c4.y, fmaf(w.w, c4.w, a4y));
            }
            int n0 = g * 5;
            sh[(n0 + 0) * D + i] = fmaxf(a0x + a0y + bav, 0.f);
            sh[(n0 + 1) * D + i] = fmaxf(a1x + a1y + bav, 0.f);
            sh[(n0 + 2) * D + i] = fmaxf(a2x + a2y + bav, 0.f);
            sh[(n0 + 3) * D + i] = fmaxf(a3x + a3y + bav, 0.f);
            sh[(n0 + 4) * D + i] = fmaxf(a4x + a4y + bav, 0.f);
        }
        __syncthreads();

        // ---- stage 2: out[nn][i] = Wb[i,:] . h[nn,:] + bb[i], max over nn
        {
            const float* wr = sWb + i * 68;
            const float* hb = sh + g * 5 * D;
            float a0x=0.f,a0y=0.f,a1x=0.f,a1y=0.f,a2x=0.f,a2y=0.f,a3x=0.f,a3y=0.f,a4x=0.f,a4y=0.f;
            #pragma unroll
            for (int j = 0; j < D; j += 4) {
                float4 w  = *(const float4*)(wr + j);
                float4 c0 = *(const float4*)(hb + j);
                float4 c1 = *(const float4*)(hb + D + j);
                float4 c2 = *(const float4*)(hb + 2 * D + j);
                float4 c3 = *(const float4*)(hb + 3 * D + j);
                float4 c4 = *(const float4*)(hb + 4 * D + j);
                a0x = fmaf(w.x, c0.x, fmaf(w.z, c0.z, a0x));
                a0y = fmaf(w.y, c0.y, fmaf(w.w, c0.w, a0y));
                a1x = fmaf(w.x, c1.x, fmaf(w.z, c1.z, a1x));
                a1y = fmaf(w.y, c1.y, fmaf(w.w, c1.w, a1y));
                a2x = fmaf(w.x, c2.x, fmaf(w.z, c2.z, a2x));
                a2y = fmaf(w.y, c2.y, fmaf(w.w, c2.w, a2y));
                a3x = fmaf(w.x, c3.x, fmaf(w.z, c3.z, a3x));
                a3y = fmaf(w.y, c3.y, fmaf(w.w, c3.w, a3y));
                a4x = fmaf(w.x, c4.x, fmaf(w.z, c4.z, a4x));
                a4y = fmaf(w.y, c4.y, fmaf(w.w, c4.w, a4y));
            }
            float m0 = fmaxf(a0x + a0y, a1x + a1y);
            float m1 = fmaxf(a2x + a2y, a3x + a3y);
            smax[t] = fmaxf(fmaxf(m0, m1), a4x + a4y) + bbv;
        }
        __syncthreads();
        if (g == 0) out[(s << 6) + i] = fmaxf(smax[i], smax[64 + i]);
    }
}

// ---------------------------------------------------------------------------
extern "C" void kernel_launch(void* const* d_in, const int* in_sizes, int n_in,
                              void* d_out, int out_size) {
    const float* cc0  = (const float*)d_in[0];
    const float* Wk   = (const float*)d_in[1];
    const float* bk   = (const float*)d_in[2];
    const float* Wq   = (const float*)d_in[3];
    const float* bq   = (const float*)d_in[4];
    const float* Wv   = (const float*)d_in[5];
    const float* bv   = (const float*)d_in[6];
    const float* cc_g = (const float*)d_in[7];
    const float* cc_b = (const float*)d_in[8];
    const float* W_ih = (const float*)d_in[9];
    const float* W_hh = (const float*)d_in[10];
    const float* b_ih = (const float*)d_in[11];
    const float* b_hh = (const float*)d_in[12];
    const float* ln_g = (const float*)d_in[13];
    const float* ln_b = (const float*)d_in[14];
    const float* W1   = (const float*)d_in[15];
    const float* b1   = (const float*)d_in[16];
    const float* W2   = (const float*)d_in[17];
    const float* b2   = (const float*)d_in[18];
    const float* Wa   = (const float*)d_in[19];
    const float* ba   = (const float*)d_in[20];
    const float* Wb   = (const float*)d_in[21];
    const float* bb   = (const float*)d_in[22];
    float* out = (float*)d_out;

    cudaFuncSetAttribute(iter_kernel,
                         cudaFuncAttributeMaxDynamicSharedMemorySize,
                         SMEM_A_BYTES);
    cudaFuncSetAttribute(mlp_kernel,
                         cudaFuncAttributeMaxDynamicSharedMemorySize,
                         SMEM_B_BYTES);

    iter_kernel<<<1, 640, SMEM_A_BYTES>>>(cc0, Wk, bk, Wq, bq, Wv, bv,
                                          cc_g, cc_b, W_ih, W_hh, b_ih, b_hh,
                                          ln_g, ln_b, W1, b1, W2, b2);
    mlp_kernel<<<MLP_NBLK, 128, SMEM_B_BYTES>>>(Wa, ba, Wb, bb, out);
}

// round 9
// speedup vs baseline: 1.0888x; 1.0888x over previous
#include <cuda_runtime.h>
#include <cuda_bf16.h>
#include <math.h>
#include <cstdint>

#define D   64
#define NC  10
#define NS  4096
#define NCB 147              // mlp compute blocks (blockIdx 1..147)

__device__ __align__(16) float g_cc[NC * D];
__device__ int g_flag;

__device__ __forceinline__ void cp_async16(float* dst_smem, const float4* src) {
    unsigned int dst = (unsigned int)__cvta_generic_to_shared(dst_smem);
    asm volatile("cp.async.cg.shared.global [%0], [%1], 16;" :: "r"(dst), "l"(src));
}
__device__ __forceinline__ float fast_sigmoid(float x) { return 1.f / (1.f + __expf(-x)); }
__device__ __forceinline__ float fast_tanh(float x) {
    float e2 = __expf(2.f * x);
    return 1.f - 2.f / (e2 + 1.f);
}

// ---------------------------------------------------------------------------
// shared helpers for the iter role (640 threads)
// ---------------------------------------------------------------------------
template<int R, int C>
__device__ __forceinline__ void stage_async(const float* __restrict__ W, float* s, int t) {
    const float4* g4 = (const float4*)W;
    constexpr int NF4 = R * C / 4;
    #pragma unroll
    for (int f = t; f < NF4; f += 640) {
        int r = (4 * f) / C;
        int c = (4 * f) % C;
        cp_async16(s + r * (C + 4) + c, g4 + f);
    }
}

template<int ODIM, int INNER, int ACT>
__device__ __forceinline__ void mmr(const float* __restrict__ X,
                                    const float* __restrict__ sW,
                                    const float* __restrict__ B,
                                    float* __restrict__ out, int t) {
    constexpr int STR = INNER + 4;
    if (t < ODIM * 2) {
        int o  = t % ODIM;
        int n0 = (t / ODIM) * 5;
        const float* w  = sW + o * STR;
        const float* xb = X + n0 * INNER;
        float a0x=0.f,a0y=0.f,a1x=0.f,a1y=0.f,a2x=0.f,a2y=0.f,a3x=0.f,a3y=0.f,a4x=0.f,a4y=0.f;
        #pragma unroll
        for (int j = 0; j < INNER; j += 4) {
            float4 wv = *(const float4*)(w + j);
            float4 x0 = *(const float4*)(xb + j);
            float4 x1 = *(const float4*)(xb + INNER + j);
            float4 x2 = *(const float4*)(xb + 2 * INNER + j);
            float4 x3 = *(const float4*)(xb + 3 * INNER + j);
            float4 x4 = *(const float4*)(xb + 4 * INNER + j);
            a0x = fmaf(wv.x, x0.x, fmaf(wv.z, x0.z, a0x));
            a0y = fmaf(wv.y, x0.y, fmaf(wv.w, x0.w, a0y));
            a1x = fmaf(wv.x, x1.x, fmaf(wv.z, x1.z, a1x));
            a1y = fmaf(wv.y, x1.y, fmaf(wv.w, x1.w, a1y));
            a2x = fmaf(wv.x, x2.x, fmaf(wv.z, x2.z, a2x));
            a2y = fmaf(wv.y, x2.y, fmaf(wv.w, x2.w, a2y));
            a3x = fmaf(wv.x, x3.x, fmaf(wv.z, x3.z, a3x));
            a3y = fmaf(wv.y, x3.y, fmaf(wv.w, x3.w, a3y));
            a4x = fmaf(wv.x, x4.x, fmaf(wv.z, x4.z, a4x));
            a4y = fmaf(wv.y, x4.y, fmaf(wv.w, x4.w, a4y));
        }
        float bo = B[o];
        float r0 = a0x + a0y + bo, r1 = a1x + a1y + bo, r2 = a2x + a2y + bo;
        float r3 = a3x + a3y + bo, r4 = a4x + a4y + bo;
        if (ACT) {
            r0 = fmaxf(r0, 0.f); r1 = fmaxf(r1, 0.f); r2 = fmaxf(r2, 0.f);
            r3 = fmaxf(r3, 0.f); r4 = fmaxf(r4, 0.f);
        }
        out[(n0 + 0) * ODIM + o] = r0;
        out[(n0 + 1) * ODIM + o] = r1;
        out[(n0 + 2) * ODIM + o] = r2;
        out[(n0 + 3) * ODIM + o] = r3;
        out[(n0 + 4) * ODIM + o] = r4;
    }
}

__device__ __forceinline__ void lnw(const float* __restrict__ X,
                                    const float* __restrict__ gma,
                                    const float* __restrict__ bta,
                                    float* __restrict__ out,
                                    float* sred, int t) {
    if (t < 320) {
        int w = t >> 5, l = t & 31;
        float v0 = X[w * 64 + l], v1 = X[w * 64 + 32 + l];
        float s = v0 + v1, s2 = v0 * v0 + v1 * v1;
        #pragma unroll
        for (int off = 16; off; off >>= 1) {
            s  += __shfl_xor_sync(0xffffffffu, s, off);
            s2 += __shfl_xor_sync(0xffffffffu, s2, off);
        }
        if (l == 0) {
            float m = s * (1.f / 64.f);
            sred[w]      = m;
            sred[16 + w] = rsqrtf(s2 * (1.f / 64.f) - m * m + 1e-5f);
        }
    }
    __syncthreads();
    int n = t >> 6, ii = t & 63;
    out[t] = (X[t] - sred[n]) * sred[16 + n] * gma[ii] + bta[ii];
    __syncthreads();
}

// ---------------------------------------------------------------------------
// mlp lane helpers
// ---------------------------------------------------------------------------
__device__ __forceinline__ void lane_issue(const float* __restrict__ gW, int slot,
                                           float* dst, int lt) {
    const float4* g4 = (const float4*)(gW + (size_t)slot * 4096);
    #pragma unroll
    for (int p = 0; p < 8; p++) {
        int f = lt + p * 128;
        int rr = f >> 4, cc = (f & 15) << 2;
        cp_async16(dst + rr * 68 + cc, g4 + f);
    }
}

// dot of 5 cluster rows against one weight row (all smem)
__device__ __forceinline__ void dot5(const float* __restrict__ wr,
                                     const float* __restrict__ xb,
                                     float& r0, float& r1, float& r2,
                                     float& r3, float& r4) {
    float a0x=0.f,a0y=0.f,a1x=0.f,a1y=0.f,a2x=0.f,a2y=0.f,a3x=0.f,a3y=0.f,a4x=0.f,a4y=0.f;
    #pragma unroll
    for (int j = 0; j < D; j += 4) {
        float4 w  = *(const float4*)(wr + j);
        float4 c0 = *(const float4*)(xb + j);
        float4 c1 = *(const float4*)(xb + D + j);
        float4 c2 = *(const float4*)(xb + 2 * D + j);
        float4 c3 = *(const float4*)(xb + 3 * D + j);
        float4 c4 = *(const float4*)(xb + 4 * D + j);
        a0x = fmaf(w.x, c0.x, fmaf(w.z, c0.z, a0x));
        a0y = fmaf(w.y, c0.y, fmaf(w.w, c0.w, a0y));
        a1x = fmaf(w.x, c1.x, fmaf(w.z, c1.z, a1x));
        a1y = fmaf(w.y, c1.y, fmaf(w.w, c1.w, a1y));
        a2x = fmaf(w.x, c2.x, fmaf(w.z, c2.z, a2x));
        a2y = fmaf(w.y, c2.y, fmaf(w.w, c2.w, a2y));
        a3x = fmaf(w.x, c3.x, fmaf(w.z, c3.z, a3x));
        a3y = fmaf(w.y, c3.y, fmaf(w.w, c3.w, a3y));
        a4x = fmaf(w.x, c4.x, fmaf(w.z, c4.z, a4x));
        a4y = fmaf(w.y, c4.y, fmaf(w.w, c4.w, a4y));
    }
    r0 = a0x + a0y; r1 = a1x + a1y; r2 = a2x + a2y; r3 = a3x + a3y; r4 = a4x + a4y;
}

// ---------------------------------------------------------------------------
// Fused kernel: block 0 = iter, blocks 1..147 = mlp (5 lanes x 128 threads).
// Dynamic smem 219264 bytes. 148 blocks <= 152 SMs -> all co-resident.
// ---------------------------------------------------------------------------
#define SMEM_BYTES 219264

__global__ void __launch_bounds__(640, 1)
fused_kernel(const float* __restrict__ cc0,
             const float* __restrict__ Wk, const float* __restrict__ bk,
             const float* __restrict__ Wq, const float* __restrict__ bq,
             const float* __restrict__ Wv, const float* __restrict__ bv,
             const float* __restrict__ cc_g, const float* __restrict__ cc_b,
             const float* __restrict__ W_ih, const float* __restrict__ W_hh,
             const float* __restrict__ b_ih, const float* __restrict__ b_hh,
             const float* __restrict__ ln_g, const float* __restrict__ ln_b,
             const float* __restrict__ W1, const float* __restrict__ b1,
             const float* __restrict__ W2, const float* __restrict__ b2,
             const float* __restrict__ Wa, const float* __restrict__ ba,
             const float* __restrict__ Wb, const float* __restrict__ bb,
             float* __restrict__ out) {
    extern __shared__ float sm[];
    const int t = threadIdx.x;

    if (blockIdx.x == 0) {
        // ================= iter role =================
        float* swq  = sm;
        float* swih = sm + 4352;
        float* swhh = sm + 17408;
        float* sw1  = sm + 30464;
        float* sw2  = sm + 39168;
        float* scc  = sm + 47616;
        float* sk   = sm + 48256;
        float* sv   = sm + 48896;
        float* sq   = sm + 49536;
        float* sxu  = sm + 50176;
        float* sgi  = sm + 50816;
        float* sgh  = sm + 52736;
        float* sattn= sm + 54656;
        float* sred = sm + 54784;

        const int n  = t >> 6;
        const int ii = t & 63;

        stage_async<64,  64 >(Wq,   swq,  t);
        stage_async<192, 64 >(W_ih, swih, t);
        stage_async<192, 64 >(W_hh, swhh, t);
        stage_async<128, 64 >(W1,   sw1,  t);
        stage_async<64,  128>(W2,   sw2,  t);
        asm volatile("cp.async.commit_group;");

        scc[t] = cc0[t];

        // k, v directly from gmem (overlaps weight stream)
        {
            const float4* ccr = (const float4*)(cc0 + n * 64);
            const float4* wkr = (const float4*)(Wk  + ii * 64);
            const float4* wvr = (const float4*)(Wv  + ii * 64);
            float kx = 0.f, ky = 0.f, vx = 0.f, vy = 0.f;
            #pragma unroll
            for (int j = 0; j < 16; j++) {
                float4 c4 = ccr[j];
                float4 k4 = wkr[j];
                float4 v4 = wvr[j];
                kx = fmaf(c4.x, k4.x, fmaf(c4.z, k4.z, kx));
                ky = fmaf(c4.y, k4.y, fmaf(c4.w, k4.w, ky));
                vx = fmaf(c4.x, v4.x, fmaf(c4.z, v4.z, vx));
                vy = fmaf(c4.y, v4.y, fmaf(c4.w, v4.w, vy));
            }
            sk[t] = kx + ky + bk[ii];
            sv[t] = vx + vy + bv[ii];
        }
        asm volatile("cp.async.wait_group 0;" ::: "memory");
        __syncthreads();

        for (int it = 0; it < 3; it++) {
            lnw(scc, cc_g, cc_b, sxu, sred, t);
            // q-mm and gh-mm concurrently (disjoint threads, disjoint smem)
            if (t < 128)       mmr<64, 64, 0>(sxu, swq, bq, sq, t);
            else if (t < 512)  mmr<192, 64, 0>(scc, swhh, b_hh, sgh, t - 128);
            __syncthreads();

            if (t < 100) {
                int an = t / 10, am = t % 10;
                const float* kr = sk + an * D;
                const float* qr = sq + am * D;
                float ax = 0.f, ay = 0.f, az = 0.f, aw = 0.f;
                #pragma unroll
                for (int j = 0; j < D; j += 4) {
                    float4 kv = *(const float4*)(kr + j);
                    float4 qv = *(const float4*)(qr + j);
                    ax = fmaf(kv.x, qv.x, ax);
                    ay = fmaf(kv.y, qv.y, ay);
                    az = fmaf(kv.z, qv.z, az);
                    aw = fmaf(kv.w, qv.w, aw);
                }
                sattn[an * 10 + am] = ((ax + ay) + (az + aw)) * 0.125f;
            }
            __syncthreads();
            if (t < 10) {   // softmax over axis 0 (column m = t)
                float mx = -1e30f;
                #pragma unroll
                for (int a = 0; a < 10; a++) mx = fmaxf(mx, sattn[a * 10 + t]);
                float ss = 0.f;
                #pragma unroll
                for (int a = 0; a < 10; a++) {
                    float e = __expf(sattn[a * 10 + t] - mx);
                    sattn[a * 10 + t] = e;
                    ss += e;
                }
                float inv = 1.f / ss;
                #pragma unroll
                for (int a = 0; a < 10; a++)
                    sattn[a * 10 + t] = sattn[a * 10 + t] * inv + 1e-8f;
            }
            __syncthreads();
            if (t < 10) {   // renormalize rows (row an = t)
                float ss = 0.f;
                #pragma unroll
                for (int m = 0; m < 10; m++) ss += sattn[t * 10 + m];
                float inv = 1.f / ss;
                #pragma unroll
                for (int m = 0; m < 10; m++) sattn[t * 10 + m] *= inv;
            }
            __syncthreads();
            {   // updates = attn @ v
                float u = 0.f;
                #pragma unroll
                for (int m = 0; m < 10; m++)
                    u = fmaf(sattn[n * 10 + m], sv[m * D + ii], u);
                sxu[t] = u;
            }
            __syncthreads();

            mmr<192, 64, 0>(sxu, swih, b_ih, sgi, t);
            __syncthreads();
            {
                float ir  = sgi[n * 192 + ii];
                float iz  = sgi[n * 192 + 64 + ii];
                float in_ = sgi[n * 192 + 128 + ii];
                float hr  = sgh[n * 192 + ii];
                float hz  = sgh[n * 192 + 64 + ii];
                float hn  = sgh[n * 192 + 128 + ii];
                float r  = fast_sigmoid(ir + hr);
                float z  = fast_sigmoid(iz + hz);
                float nn = fast_tanh(in_ + r * hn);
                scc[t] = (1.f - z) * nn + z * scc[t];
            }
            __syncthreads();

            lnw(scc, ln_g, ln_b, sxu, sred, t);
            mmr<128, 64, 1>(sxu, sw1, b1, sgi, t);
            __syncthreads();
            mmr<64, 128, 0>(sgi, sw2, b2, sgh, t);
            __syncthreads();
            scc[t] += sgh[t];
            __syncthreads();
        }

        g_cc[t] = scc[t];
        __threadfence();
        __syncthreads();
        if (t == 0) atomicExch(&g_flag, 1);
        return;
    }

    // ================= mlp role =================
    // smem: laneW[5][8704] @0, scc @43520 (640), sh @44160 (5x640), smax @47360 (5x128)
    const int cb = blockIdx.x - 1;                 // 0..146
    const int q  = NS / NCB;                       // 27
    const int r  = NS % NCB;                       // 127
    const int s0    = cb * q + (cb < r ? cb : r);
    const int count = q + (cb < r ? 1 : 0);

    const int lane = t >> 7;        // 0..4
    const int lt   = t & 127;
    const int i    = lt & 63;
    const int g    = lt >> 6;

    // lane slot sub-range
    const int q2 = count / 5, r2 = count % 5;
    const int ls0    = s0 + lane * q2 + (lane < r2 ? lane : r2);
    const int lcount = q2 + (lane < r2 ? 1 : 0);

    // 1. prefetch the whole block range into L2 (runs under iter)
    {
        const int nlines = count * 256;            // 256 x 128B lines per slot
        for (int idx = t; idx < nlines; idx += 640) {
            int slot = s0 + (idx >> 8);
            int line = idx & 255;
            const float* p;
            if (line < 128) p = Wa + (size_t)slot * 4096 + line * 32;
            else            p = Wb + (size_t)slot * 4096 + (line - 128) * 32;
            asm volatile("prefetch.global.L2 [%0];" :: "l"(p));
        }
    }

    // 2. first slot weights via cp.async (also under iter)
    float* Wab = sm + lane * 8704;
    if (lcount > 0) {
        lane_issue(Wa, ls0, Wab, lt);
        lane_issue(Wb, ls0, Wab + 4352, lt);
    }
    asm volatile("cp.async.commit_group;");

    // 3. wait for iter's g_cc
    if (t == 0) {
        while (atomicAdd(&g_flag, 0) == 0) { __nanosleep(256); }
    }
    __syncthreads();
    __threadfence();

    // 4. stage scc (L2-only loads; g_cc never in this SM's L1)
    float* scc = sm + 43520;
    #pragma unroll
    for (int p = t; p < 160; p += 640)
        ((float4*)scc)[p] = __ldcg(((const float4*)g_cc) + p);
    __syncthreads();

    float* shl = sm + 44160 + lane * 640;
    float* smx = sm + 47360 + lane * 128;

    for (int k2 = 0; k2 < lcount; k2++) {
        const int s = ls0 + k2;
        asm volatile("cp.async.wait_group 0;" ::: "memory");
        asm volatile("bar.sync %0, 128;" :: "r"(lane + 1) : "memory");

        float bav = __ldg(ba + (s << 6) + i);
        float bbv = __ldg(bb + (s << 6) + i);

        // stage 1: h[nn][i] = relu(Wa[i,:].cc[nn,:] + ba[i]) for 5 nn
        {
            float r0, r1, r2v, r3, r4;
            dot5(Wab + i * 68, scc + g * 5 * D, r0, r1, r2v, r3, r4);
            int n0 = g * 5;
            shl[(n0 + 0) * D + i] = fmaxf(r0 + bav, 0.f);
            shl[(n0 + 1) * D + i] = fmaxf(r1 + bav, 0.f);
            shl[(n0 + 2) * D + i] = fmaxf(r2v + bav, 0.f);
            shl[(n0 + 3) * D + i] = fmaxf(r3 + bav, 0.f);
            shl[(n0 + 4) * D + i] = fmaxf(r4 + bav, 0.f);
        }
        asm volatile("bar.sync %0, 128;" :: "r"(lane + 1) : "memory");
        // Wa buffer free now -> start next slot's Wa under stage 2
        if (k2 + 1 < lcount) lane_issue(Wa, s + 1, Wab, lt);

        // stage 2: out[nn][i] = Wb[i,:].h[nn,:] + bb[i], max over nn
        {
            float r0, r1, r2v, r3, r4;
            dot5(Wab + 4352 + i * 68, shl + g * 5 * D, r0, r1, r2v, r3, r4);
            float m0 = fmaxf(r0, r1);
            float m1 = fmaxf(r2v, r3);
            smx[lt] = fmaxf(fmaxf(m0, m1), r4) + bbv;
        }
        asm volatile("bar.sync %0, 128;" :: "r"(lane + 1) : "memory");
        if (g == 0) out[(s << 6) + i] = fmaxf(smx[i], smx[64 + i]);
        // Wb buffer free now
        if (k2 + 1 < lcount) {
            lane_issue(Wb, s + 1, Wab + 4352, lt);
            asm volatile("cp.async.commit_group;");
        }
    }
}

__global__ void init_kernel() { g_flag = 0; }

// ---------------------------------------------------------------------------
extern "C" void kernel_launch(void* const* d_in, const int* in_sizes, int n_in,
                              void* d_out, int out_size) {
    const float* cc0  = (const float*)d_in[0];
    const float* Wk   = (const float*)d_in[1];
    const float* bk   = (const float*)d_in[2];
    const float* Wq   = (const float*)d_in[3];
    const float* bq   = (const float*)d_in[4];
    const float* Wv   = (const float*)d_in[5];
    const float* bv   = (const float*)d_in[6];
    const float* cc_g = (const float*)d_in[7];
    const float* cc_b = (const float*)d_in[8];
    const float* W_ih = (const float*)d_in[9];
    const float* W_hh = (const float*)d_in[10];
    const float* b_ih = (const float*)d_in[11];
    const float* b_hh = (const float*)d_in[12];
    const float* ln_g = (const float*)d_in[13];
    const float* ln_b = (const float*)d_in[14];
    const float* W1   = (const float*)d_in[15];
    const float* b1   = (const float*)d_in[16];
    const float* W2   = (const float*)d_in[17];
    const float* b2   = (const float*)d_in[18];
    const float* Wa   = (const float*)d_in[19];
    const float* ba   = (const float*)d_in[20];
    const float* Wb   = (const float*)d_in[21];
    const float* bb   = (const float*)d_in[22];
    float* out = (float*)d_out;

    cudaFuncSetAttribute(fused_kernel,
                         cudaFuncAttributeMaxDynamicSharedMemorySize,
                         SMEM_BYTES);

    init_kernel<<<1, 1>>>();
    fused_kernel<<<1 + NCB, 640, SMEM_BYTES>>>(
        cc0, Wk, bk, Wq, bq, Wv, bv, cc_g, cc_b,
        W_ih, W_hh, b_ih, b_hh, ln_g, ln_b, W1, b1, W2, b2,
        Wa, ba, Wb, bb, out);
}